// round 14
// baseline (speedup 1.0000x reference)
#include <cuda_runtime.h>

// Inputs: (8,3,512,512) fp32 x3 (general, ir, vi). Output: 1 float (mean L1).
#define WD   512
#define HT   512
#define NPL  24
#define CT   128         // output cols per block
#define CTP  64          // output col pairs
#define ABP  69          // ab col pairs (138 cols)
#define NTH  448         // 14 warps
#define NWARP 14
#define BANDA 172        // bands: 172,172,168
#define RPB  5           // rows per pipeline batch

constexpr float EPSV   = 1e-6f;
constexpr float INV_KK = 1.0f / 121.0f;
constexpr int   EPLANE = WD * HT;
constexpr float SCALE  = 1.0f / (float)(NPL * EPLANE);

// ---- shared layout (float units; 16B-aligned offsets) ---------------------
constexpr int OFF_HC   = 0;                       // [3][11][ABP] float4 = 9108
constexpr int OFF_AB   = 9108;                    // [2][3][RPB][ABP] float4 = 8280
constexpr int OFF_HAC  = 17388;                   // [3][11][CTP] float4 = 8448
constexpr int OFF_FB   = 25836;                   // [2][2][RPB][CTP] float2 = 2560
constexpr int OFF_RED  = 28396;
constexpr int SMEM_FLOATS = OFF_RED + NWARP;      // 28410
constexpr int SMEM_BYTES  = SMEM_FLOATS * 4;      // 113640 B -> 2 blocks/SM

__device__ __forceinline__ float fast_rcp(float x) {
    float r;
    asm("rcp.approx.f32 %0, %1;" : "=f"(r) : "f"(x));
    return r;
}

// ---- packed f32x2 helpers (Blackwell) -------------------------------------
__device__ __forceinline__ float2 padd(float2 a, float2 b) {
    unsigned long long ra = *reinterpret_cast<unsigned long long*>(&a);
    unsigned long long rb = *reinterpret_cast<unsigned long long*>(&b);
    unsigned long long rd;
    asm("add.rn.f32x2 %0, %1, %2;" : "=l"(rd) : "l"(ra), "l"(rb));
    return *reinterpret_cast<float2*>(&rd);
}
__device__ __forceinline__ float2 pmul(float2 a, float2 b) {
    unsigned long long ra = *reinterpret_cast<unsigned long long*>(&a);
    unsigned long long rb = *reinterpret_cast<unsigned long long*>(&b);
    unsigned long long rd;
    asm("mul.rn.f32x2 %0, %1, %2;" : "=l"(rd) : "l"(ra), "l"(rb));
    return *reinterpret_cast<float2*>(&rd);
}
__device__ __forceinline__ float2 pfma(float2 a, float2 b, float2 c) {
    unsigned long long ra = *reinterpret_cast<unsigned long long*>(&a);
    unsigned long long rb = *reinterpret_cast<unsigned long long*>(&b);
    unsigned long long rc = *reinterpret_cast<unsigned long long*>(&c);
    unsigned long long rd;
    asm("fma.rn.f32x2 %0, %1, %2, %3;" : "=l"(rd) : "l"(ra), "l"(rb), "l"(rc));
    return *reinterpret_cast<float2*>(&rd);
}
__device__ __forceinline__ float2 psub(float2 a, float2 b) {   // a - b
    return pfma(b, make_float2(-1.f, -1.f), a);
}

struct IterState {
    float2 SA, SB;               // P2 vertical running sums (s1,s2) per col
    float2 TA, TB;               // P3a vertical running sums (ha,hb) per col
    float2 f2s[RPB];             // plane-2 f carry (1 iter)
    float  lacc;
};

// Load one 12-wide x window (6 float2) for row at rowp; zero if !rowOK.
__device__ __forceinline__ void load_win(
    float2* L, const float* rowp, bool rowOK,
    bool okc0, bool okc1, bool okc2, bool okc3, bool okc4, bool okc5)
{
    if (rowOK) {
        L[0] = okc0 ? __ldg((const float2*)(rowp))      : make_float2(0.f,0.f);
        L[1] = okc1 ? __ldg((const float2*)(rowp + 2))  : make_float2(0.f,0.f);
        L[2] = okc2 ? __ldg((const float2*)(rowp + 4))  : make_float2(0.f,0.f);
        L[3] = okc3 ? __ldg((const float2*)(rowp + 6))  : make_float2(0.f,0.f);
        L[4] = okc4 ? __ldg((const float2*)(rowp + 8))  : make_float2(0.f,0.f);
        L[5] = okc5 ? __ldg((const float2*)(rowp + 10)) : make_float2(0.f,0.f);
    } else {
        L[0] = L[1] = L[2] = L[3] = L[4] = L[5] = make_float2(0.f, 0.f);
    }
}

// One pipeline iteration. STEADY=true drops all row-range predicates.
template <bool STEADY>
__device__ __forceinline__ void iter_body(
    int i, int y0, int band, int c0, int pmax,
    bool isA, const float* xpA, int p2p, int p2j,
    bool isB, const float* xpB, int p3p, int p3i,
    bool okc0, bool okc1, bool okc2, bool okc3, bool okc4, bool okc5,
    bool okab0, bool okab1,
    float4* hc4, float4* ab4, float4* hac4, float2* fb2,
    IterState& st)
{
    const int Rb = y0 - 10 + RPB * i;
    const float2 KK2 = make_float2(INV_KK, INV_KK);

    // ================= P2: batch i =========================================
    if (isA && (STEADY || i < pmax)) {
        const int colb = c0 - 10 + 2 * p2j;
        int slot = (Rb + 22) % 11;
        float4* abw = ab4 + (i & 1) * (3 * RPB * ABP) + (p2p * RPB) * ABP + p2j;
        const float* rowp = xpA + (size_t)Rb * WD + colb;

        float2 L[6];
        load_win(L, rowp, STEADY || ((unsigned)Rb < (unsigned)HT),
                 okc0, okc1, okc2, okc3, okc4, okc5);
#pragma unroll
        for (int r = 0; r < RPB; ++r) {
            const int yi = Rb + r;
            float2 N[6];
            if (r < RPB - 1) {
                load_win(N, rowp + WD, STEADY || ((unsigned)(yi + 1) < (unsigned)HT),
                         okc0, okc1, okc2, okc3, okc4, okc5);
                rowp += WD;
            }
            float2 a1 = padd(padd(padd(L[0], L[1]), padd(L[2], L[3])),
                             padd(L[4], L[5]));
            float2 a2 = pfma(L[0], L[0],
                        pfma(L[1], L[1],
                        pfma(L[2], L[2],
                        pfma(L[3], L[3],
                        pfma(L[4], L[4], pmul(L[5], L[5]))))));
            const float s1 = a1.x + a1.y;
            const float s2 = a2.x + a2.y;
            const float e0 = L[0].x, e11 = L[5].y;
            const float2 hA = make_float2(s1 - e11, fmaf(-e11, e11, s2));
            const float2 hB = make_float2(s1 - e0,  fmaf(-e0,  e0,  s2));
            float4* rp = &hc4[(p2p * 11 + slot) * ABP + p2j];
            if (STEADY || yi >= y0 + 1) {
                float4 o = *rp;
                st.SA = psub(st.SA, make_float2(o.x, o.y));
                st.SB = psub(st.SB, make_float2(o.z, o.w));
            }
            *rp = make_float4(hA.x, hA.y, hB.x, hB.y);
            st.SA = padd(st.SA, hA);
            st.SB = padd(st.SB, hB);
            if (STEADY || yi >= y0) {
                const int ya = yi - 5;
                float4 v = make_float4(0.f, 0.f, 0.f, 0.f);
                if (STEADY || (unsigned)ya < (unsigned)HT) {
                    if (okab0) {
                        float2 mc  = pmul(st.SA, KK2);       // (mean, corr)
                        float var  = fmaf(-mc.x, mc.x, mc.y);
                        float rr   = fast_rcp(var + EPSV);
                        v.x = var * rr; v.y = mc.x * (EPSV * rr);
                    }
                    if (okab1) {
                        float2 mc  = pmul(st.SB, KK2);
                        float var  = fmaf(-mc.x, mc.x, mc.y);
                        float rr   = fast_rcp(var + EPSV);
                        v.z = var * rr; v.w = mc.x * (EPSV * rr);
                    }
                }
                abw[r * ABP] = v;
            }
            if (r < RPB - 1) {
#pragma unroll
                for (int k = 0; k < 6; ++k) L[k] = N[k];
            }
            slot = (slot + 1 == 11) ? 0 : slot + 1;
        }
    }

    // ================= P3a: batch i-1 + f + loss ===========================
    if (isB) {
        const int cx = c0 + 2 * p3i;
        float2 xv[RPB];
#pragma unroll
        for (int r = 0; r < RPB; ++r) {
            const int yo = Rb - 15 + r;
            xv[r] = (STEADY || (yo >= y0 && yo < y0 + band))
                  ? __ldg((const float2*)(xpB + (size_t)yo * WD + cx))
                  : make_float2(0.f, 0.f);
        }
        if (p3p == 2) {
            // combine batch i-2 (f2s registers + fb written at iter i-1)
            const float2* fa  = fb2 + (((i - 1) & 1) * 2 + 0) * (RPB * CTP) + p3i;
            const float2* fbv = fb2 + (((i - 1) & 1) * 2 + 1) * (RPB * CTP) + p3i;
#pragma unroll
            for (int r = 0; r < RPB; ++r) {
                const int yr = RPB * i - 30 + r;
                if (STEADY || (yr >= 0 && yr < band)) {
                    float2 a01 = fa[r * CTP];
                    float2 b01 = fbv[r * CTP];
                    st.lacc += fabsf(st.f2s[r].x - fmaxf(a01.x, b01.x));
                    st.lacc += fabsf(st.f2s[r].y - fmaxf(a01.y, b01.y));
                }
            }
        }
        const float4* abr = ab4 + ((i - 1) & 1) * (3 * RPB * ABP)
                            + (p3p * RPB) * ABP + p3i;
        int slot = (Rb + 12) % 11;                 // slot(ya), ya = Rb-10+r
#pragma unroll
        for (int r = 0; r < RPB; ++r) {
            const int yb = Rb - 5 + r;
            if (STEADY || (yb >= y0 && yb <= y0 + band + 9)) {
                const int ya = yb - 5;
                const float4* ap = abr + r * ABP;
                float4 w0 = ap[0], w1 = ap[1], w2 = ap[2];
                float4 w3 = ap[3], w4 = ap[4], w5 = ap[5];
                const float2 p0 = make_float2(w0.x, w0.y), q0 = make_float2(w0.z, w0.w);
                const float2 p1 = make_float2(w1.x, w1.y), q1 = make_float2(w1.z, w1.w);
                const float2 p2 = make_float2(w2.x, w2.y), q2 = make_float2(w2.z, w2.w);
                const float2 p3 = make_float2(w3.x, w3.y), q3 = make_float2(w3.z, w3.w);
                const float2 p4 = make_float2(w4.x, w4.y), q4 = make_float2(w4.z, w4.w);
                const float2 p5 = make_float2(w5.x, w5.y), q5 = make_float2(w5.z, w5.w);
                float2 H = padd(padd(padd(padd(p0, q0), padd(p1, q1)),
                                     padd(padd(p2, q2), padd(p3, q3))),
                                padd(padd(p4, q4), padd(p5, q5)));
                const float2 hA = psub(H, q5);
                const float2 hB = psub(H, p0);
                float4* rp = &hac4[(p3p * 11 + slot) * CTP + p3i];
                if (STEADY || ya >= y0 + 6) {
                    float4 o = *rp;
                    st.TA = psub(st.TA, make_float2(o.x, o.y));
                    st.TB = psub(st.TB, make_float2(o.z, o.w));
                }
                *rp = make_float4(hA.x, hA.y, hB.x, hB.y);
                st.TA = padd(st.TA, hA);
                st.TB = padd(st.TB, hB);
                const int yo = ya - 5;
                if (STEADY || (yo >= y0 && yo < y0 + band)) {
                    float2 mA = pmul(st.TA, KK2);     // (ma0, mb0)
                    float2 mB = pmul(st.TB, KK2);     // (ma1, mb1)
                    float2 xr = xv[r];
                    float f0 = xr.x - fmaf(mA.x, xr.x, mA.y);
                    float f1 = xr.y - fmaf(mB.x, xr.y, mB.y);
                    if (p3p < 2) {
                        fb2[(((i & 1) * 2 + p3p) * RPB + r) * CTP + p3i] =
                            make_float2(fabsf(f0), fabsf(f1));
                    } else {
                        st.f2s[r] = make_float2(f0, f1);
                    }
                }
            }
            slot = (slot + 1 == 11) ? 0 : slot + 1;
        }
    }
    __syncthreads();
}

__global__ void __launch_bounds__(NTH, 2) fused_loss(
    const float* __restrict__ gen, const float* __restrict__ ir,
    const float* __restrict__ vi, float* __restrict__ out)
{
    extern __shared__ float smf[];
    const int t    = threadIdx.x;
    const int c0   = blockIdx.x * CT;
    const int y0   = blockIdx.y * BANDA;
    const int band = (blockIdx.y == 2) ? (HT - 2 * BANDA) : BANDA;
    const size_t pbase = (size_t)blockIdx.z * EPLANE;

    float4* hc4  = (float4*)(smf + OFF_HC);        // [p][slot11][ABP]
    float4* ab4  = (float4*)(smf + OFF_AB);        // [buf][p][r][ABP]
    float4* hac4 = (float4*)(smf + OFF_HAC);       // [p][slot11][CTP]
    float2* fb2  = (float2*)(smf + OFF_FB);        // [buf][p01][r][CTP]
    float*  red  = smf + OFF_RED;

    // roles: P2 = threads 0..206, P3a = threads 224..415
    const bool isA = t < 3 * ABP;                  // 207 threads
    const int  p2p = t / ABP;
    const int  p2j = t - p2p * ABP;
    const int  tb  = t - 224;
    const bool isB = (tb >= 0) && (tb < 3 * CTP);  // 192 threads
    const int  p3p = (tb >= 0) ? (tb >> 6) : 0;
    const int  p3i = (tb >= 0) ? (tb & (CTP - 1)) : 0;

    const float* xpA = (p2p == 0) ? (ir + pbase) : (p2p == 1) ? (vi + pbase) : (gen + pbase);
    const float* xpB = (p3p == 0) ? (ir + pbase) : (p3p == 1) ? (vi + pbase) : (gen + pbase);

    // thread-invariant column predicates
    const int cbase = c0 - 10 + 2 * p2j;
    const bool okc0 = (unsigned)(cbase)      < (unsigned)WD;
    const bool okc1 = (unsigned)(cbase + 2)  < (unsigned)WD;
    const bool okc2 = (unsigned)(cbase + 4)  < (unsigned)WD;
    const bool okc3 = (unsigned)(cbase + 6)  < (unsigned)WD;
    const bool okc4 = (unsigned)(cbase + 8)  < (unsigned)WD;
    const bool okc5 = (unsigned)(cbase + 10) < (unsigned)WD;
    const int  cab  = c0 - 5 + 2 * p2j;
    const bool okab0 = (unsigned)cab       < (unsigned)WD;
    const bool okab1 = (unsigned)(cab + 1) < (unsigned)WD;

    IterState st;
    st.SA = st.SB = st.TA = st.TB = make_float2(0.f, 0.f);
#pragma unroll
    for (int r = 0; r < RPB; ++r) st.f2s[r] = make_float2(0.f, 0.f);
    st.lacc = 0.f;

    const int jlast = (band + 18) / RPB;           // last P2 batch (38/37)
    const int pmax  = jlast + 1;                   // P2 active while i < pmax
    const int iters = jlast + 3;                   // 41 / 40
    int iSteadyEnd  = (band + 20) / RPB;           // P3b bottom bound
    {
        int b2 = (HT - y0 + 5) / RPB;              // P2 image-bottom bound
        if (b2 < iSteadyEnd) iSteadyEnd = b2;
        if (pmax < iSteadyEnd) iSteadyEnd = pmax;
        if (iSteadyEnd < 7) iSteadyEnd = 7;
    }

    for (int i = 0; i < 7; ++i)
        iter_body<false>(i, y0, band, c0, pmax, isA, xpA, p2p, p2j, isB, xpB, p3p, p3i,
                         okc0, okc1, okc2, okc3, okc4, okc5, okab0, okab1,
                         hc4, ab4, hac4, fb2, st);
    for (int i = 7; i < iSteadyEnd; ++i)
        iter_body<true>(i, y0, band, c0, pmax, isA, xpA, p2p, p2j, isB, xpB, p3p, p3i,
                        okc0, okc1, okc2, okc3, okc4, okc5, okab0, okab1,
                        hc4, ab4, hac4, fb2, st);
    for (int i = iSteadyEnd; i < iters; ++i)
        iter_body<false>(i, y0, band, c0, pmax, isA, xpA, p2p, p2j, isB, xpB, p3p, p3i,
                         okc0, okc1, okc2, okc3, okc4, okc5, okab0, okab1,
                         hc4, ab4, hac4, fb2, st);

    // ---- block reduction + atomic ----------------------------------------
    float lacc = st.lacc;
#pragma unroll
    for (int o = 16; o; o >>= 1) lacc += __shfl_down_sync(0xffffffffu, lacc, o);
    if ((t & 31) == 0) red[t >> 5] = lacc;
    __syncthreads();
    if (t == 0) {
        float v = 0.f;
#pragma unroll
        for (int w = 0; w < NWARP; ++w) v += red[w];
        atomicAdd(out, v * SCALE);
    }
}

__global__ void zero_out(float* out) { out[0] = 0.f; }

// ---------------------------------------------------------------------------
extern "C" void kernel_launch(void* const* d_in, const int* in_sizes, int n_in,
                              void* d_out, int out_size) {
    const float* gen = (const float*)d_in[0];
    const float* ir  = (const float*)d_in[1];
    const float* vi  = (const float*)d_in[2];
    float* out = (float*)d_out;

    cudaFuncSetAttribute(fused_loss, cudaFuncAttributeMaxDynamicSharedMemorySize,
                         SMEM_BYTES);

    zero_out<<<1, 1>>>(out);
    dim3 grid(WD / CT, 3, NPL);   // (4, 3, 24) = 288 blocks
    fused_loss<<<grid, NTH, SMEM_BYTES>>>(gen, ir, vi, out);
}

// round 15
// speedup vs baseline: 1.0977x; 1.0977x over previous
#include <cuda_runtime.h>

// Inputs: (8,3,512,512) fp32 x3 (general, ir, vi). Output: 1 float (mean L1).
#define WD   512
#define HT   512
#define NPL  24
#define CT   128         // output cols per block
#define CTP  64          // output col pairs
#define ABP  69          // ab col pairs (138 cols)
#define NTH  416         // 13 warps (warp 13 was idle)
#define NWARP 13
#define BANDA 172        // bands: 172,172,168
#define RPB  4

constexpr float EPSV   = 1e-6f;
constexpr float INV_KK = 1.0f / 121.0f;
constexpr int   EPLANE = WD * HT;
constexpr float SCALE  = 1.0f / (float)(NPL * EPLANE);

// ---- shared layout (float units; 16B-aligned offsets) ---------------------
constexpr int OFF_HC   = 0;                       // [3][11][ABP] float4 = 9108
constexpr int OFF_S2   = 9108;                    // [2][3][RPB][ABP] float2 = 3312
constexpr int OFF_PP   = 12420;                   // [2][3][RPB][ABP] float2 = 3312
constexpr int OFF_HAC  = 15732;                   // [3][11][CTP] float4 = 8448
constexpr int OFF_FB   = 24180;                   // [2][2][RPB][CTP] float2 = 2048
constexpr int OFF_RED  = 26228;
constexpr int SMEM_FLOATS = OFF_RED + NWARP;      // 26241
constexpr int SMEM_BYTES  = SMEM_FLOATS * 4;      // 104964 B -> 2 blocks/SM

__device__ __forceinline__ float fast_rcp(float x) {
    float r;
    asm("rcp.approx.f32 %0, %1;" : "=f"(r) : "f"(x));
    return r;
}

// ---- packed f32x2 helpers (Blackwell) -------------------------------------
__device__ __forceinline__ float2 padd(float2 a, float2 b) {
    unsigned long long ra = *reinterpret_cast<unsigned long long*>(&a);
    unsigned long long rb = *reinterpret_cast<unsigned long long*>(&b);
    unsigned long long rd;
    asm("add.rn.f32x2 %0, %1, %2;" : "=l"(rd) : "l"(ra), "l"(rb));
    return *reinterpret_cast<float2*>(&rd);
}
__device__ __forceinline__ float2 pmul(float2 a, float2 b) {
    unsigned long long ra = *reinterpret_cast<unsigned long long*>(&a);
    unsigned long long rb = *reinterpret_cast<unsigned long long*>(&b);
    unsigned long long rd;
    asm("mul.rn.f32x2 %0, %1, %2;" : "=l"(rd) : "l"(ra), "l"(rb));
    return *reinterpret_cast<float2*>(&rd);
}
__device__ __forceinline__ float2 pfma(float2 a, float2 b, float2 c) {
    unsigned long long ra = *reinterpret_cast<unsigned long long*>(&a);
    unsigned long long rb = *reinterpret_cast<unsigned long long*>(&b);
    unsigned long long rc = *reinterpret_cast<unsigned long long*>(&c);
    unsigned long long rd;
    asm("fma.rn.f32x2 %0, %1, %2, %3;" : "=l"(rd) : "l"(ra), "l"(rb), "l"(rc));
    return *reinterpret_cast<float2*>(&rd);
}
__device__ __forceinline__ float2 psub(float2 a, float2 b) {   // a - b
    return pfma(b, make_float2(-1.f, -1.f), a);
}

struct IterState {
    float2 SA, SB;               // P2 vertical running sums (s1,s2) per col
    float2 TA, TB;               // P3a vertical running sums (ha,hb) per col
    float2 f2s[RPB];             // plane-2 f carry (1 iter)
    float  lacc;
};

// Load one 12-wide x window (6 float2) for row at rowp; zero if !rowOK.
__device__ __forceinline__ void load_win(
    float2* L, const float* rowp, bool rowOK,
    bool okc0, bool okc1, bool okc2, bool okc3, bool okc4, bool okc5)
{
    if (rowOK) {
        L[0] = okc0 ? __ldg((const float2*)(rowp))      : make_float2(0.f,0.f);
        L[1] = okc1 ? __ldg((const float2*)(rowp + 2))  : make_float2(0.f,0.f);
        L[2] = okc2 ? __ldg((const float2*)(rowp + 4))  : make_float2(0.f,0.f);
        L[3] = okc3 ? __ldg((const float2*)(rowp + 6))  : make_float2(0.f,0.f);
        L[4] = okc4 ? __ldg((const float2*)(rowp + 8))  : make_float2(0.f,0.f);
        L[5] = okc5 ? __ldg((const float2*)(rowp + 10)) : make_float2(0.f,0.f);
    } else {
        L[0] = L[1] = L[2] = L[3] = L[4] = L[5] = make_float2(0.f, 0.f);
    }
}

// One pipeline iteration. STEADY=true drops all row-range predicates.
template <bool STEADY>
__device__ __forceinline__ void iter_body(
    int i, int y0, int band, int c0, int pmax,
    bool isA, const float* xpA, int p2p, int p2j,
    bool isB, const float* xpB, int p3p, int p3i,
    bool okc0, bool okc1, bool okc2, bool okc3, bool okc4, bool okc5,
    bool okab0, bool okab1,
    float4* hc4, float2* s2a, float2* ppa, float4* hac4, float2* fb2,
    IterState& st)
{
    const int Rb = y0 - 10 + 4 * i;
    const float2 KK2 = make_float2(INV_KK, INV_KK);

    // ================= P2: batch i =========================================
    if (isA && (STEADY || i < pmax)) {
        const int colb = c0 - 10 + 2 * p2j;
        int slot = (Rb + 22) % 11;
        const int abBase = ((i & 1) * 3 + p2p) * (RPB * ABP) + p2j;
        float2* s2w = s2a + abBase;
        float2* ppw = ppa + abBase;
        const float* rowp = xpA + (size_t)Rb * WD + colb;

        float2 L[6];
        load_win(L, rowp, STEADY || ((unsigned)Rb < (unsigned)HT),
                 okc0, okc1, okc2, okc3, okc4, okc5);
#pragma unroll
        for (int r = 0; r < RPB; ++r) {
            const int yi = Rb + r;
            float2 N[6];
            if (r < RPB - 1) {
                load_win(N, rowp + WD, STEADY || ((unsigned)(yi + 1) < (unsigned)HT),
                         okc0, okc1, okc2, okc3, okc4, okc5);
                rowp += WD;
            }
            float2 a1 = padd(padd(padd(L[0], L[1]), padd(L[2], L[3])),
                             padd(L[4], L[5]));
            float2 a2 = pfma(L[0], L[0],
                        pfma(L[1], L[1],
                        pfma(L[2], L[2],
                        pfma(L[3], L[3],
                        pfma(L[4], L[4], pmul(L[5], L[5]))))));
            const float s1 = a1.x + a1.y;
            const float s2 = a2.x + a2.y;
            const float e0 = L[0].x, e11 = L[5].y;
            const float2 hA = make_float2(s1 - e11, fmaf(-e11, e11, s2));
            const float2 hB = make_float2(s1 - e0,  fmaf(-e0,  e0,  s2));
            float4* rp = &hc4[(p2p * 11 + slot) * ABP + p2j];
            if (STEADY || yi >= y0 + 1) {
                float4 o = *rp;
                st.SA = psub(st.SA, make_float2(o.x, o.y));
                st.SB = psub(st.SB, make_float2(o.z, o.w));
            }
            *rp = make_float4(hA.x, hA.y, hB.x, hB.y);
            st.SA = padd(st.SA, hA);
            st.SB = padd(st.SB, hB);
            if (STEADY || yi >= y0) {
                const int ya = yi - 5;
                float2 vp = make_float2(0.f, 0.f);   // (a0, b0)
                float2 vq = make_float2(0.f, 0.f);   // (a1, b1)
                if (STEADY || (unsigned)ya < (unsigned)HT) {
                    if (okab0) {
                        float2 mc  = pmul(st.SA, KK2);       // (mean, corr)
                        float var  = fmaf(-mc.x, mc.x, mc.y);
                        float rr   = fast_rcp(var + EPSV);
                        vp = make_float2(var * rr, mc.x * (EPSV * rr));
                    }
                    if (okab1) {
                        float2 mc  = pmul(st.SB, KK2);
                        float var  = fmaf(-mc.x, mc.x, mc.y);
                        float rr   = fast_rcp(var + EPSV);
                        vq = make_float2(var * rr, mc.x * (EPSV * rr));
                    }
                }
                s2w[r * ABP] = padd(vp, vq);          // S = p + q
                ppw[r * ABP] = vp;                    // p
            }
            if (r < RPB - 1) {
#pragma unroll
                for (int k = 0; k < 6; ++k) L[k] = N[k];
            }
            slot = (slot + 1 == 11) ? 0 : slot + 1;
        }
    }

    // ================= P3a: batch i-1 + f + loss ===========================
    if (isB) {
        const int cx = c0 + 2 * p3i;
        float2 xv[RPB];
#pragma unroll
        for (int r = 0; r < RPB; ++r) {
            const int yo = Rb - 14 + r;
            xv[r] = (STEADY || (yo >= y0 && yo < y0 + band))
                  ? __ldg((const float2*)(xpB + (size_t)yo * WD + cx))
                  : make_float2(0.f, 0.f);
        }
        if (p3p == 2) {
            const float2* fa  = fb2 + (((i - 1) & 1) * 2 + 0) * (RPB * CTP) + p3i;
            const float2* fbv = fb2 + (((i - 1) & 1) * 2 + 1) * (RPB * CTP) + p3i;
#pragma unroll
            for (int r = 0; r < RPB; ++r) {
                const int yr = 4 * i - 28 + r;
                if (STEADY || (yr >= 0 && yr < band)) {
                    float2 a01 = fa[r * CTP];
                    float2 b01 = fbv[r * CTP];
                    st.lacc += fabsf(st.f2s[r].x - fmaxf(a01.x, b01.x));
                    st.lacc += fabsf(st.f2s[r].y - fmaxf(a01.y, b01.y));
                }
            }
        }
        const int abBase = (((i - 1) & 1) * 3 + p3p) * (RPB * ABP) + p3i;
        const float2* srr = s2a + abBase;
        const float2* prr = ppa + abBase;
        int slot = (Rb + 13) % 11;                 // slot(ya), ya = Rb-9+r
#pragma unroll
        for (int r = 0; r < RPB; ++r) {
            const int yb = Rb - 4 + r;
            if (STEADY || (yb >= y0 && yb <= y0 + band + 9)) {
                const int ya = yb - 5;
                const float2* sp = srr + r * ABP;
                const float2 S0 = sp[0], S1 = sp[1], S2v = sp[2];
                const float2 S3 = sp[3], S4 = sp[4], S5 = sp[5];
                const float2 P0 = prr[r * ABP];
                const float2 P5 = prr[r * ABP + 5];
                float2 H = padd(padd(padd(S0, S1), padd(S2v, S3)),
                                padd(S4, S5));                 // 5 padd
                const float2 q5 = psub(S5, P5);
                const float2 hA = psub(H, q5);
                const float2 hB = psub(H, P0);
                float4* rp = &hac4[(p3p * 11 + slot) * CTP + p3i];
                if (STEADY || ya >= y0 + 6) {
                    float4 o = *rp;
                    st.TA = psub(st.TA, make_float2(o.x, o.y));
                    st.TB = psub(st.TB, make_float2(o.z, o.w));
                }
                *rp = make_float4(hA.x, hA.y, hB.x, hB.y);
                st.TA = padd(st.TA, hA);
                st.TB = padd(st.TB, hB);
                const int yo = ya - 5;
                if (STEADY || (yo >= y0 && yo < y0 + band)) {
                    float2 mA = pmul(st.TA, KK2);     // (ma0, mb0)
                    float2 mB = pmul(st.TB, KK2);     // (ma1, mb1)
                    float2 xr = xv[r];
                    float f0 = xr.x - fmaf(mA.x, xr.x, mA.y);
                    float f1 = xr.y - fmaf(mB.x, xr.y, mB.y);
                    if (p3p < 2) {
                        fb2[(((i & 1) * 2 + p3p) * RPB + r) * CTP + p3i] =
                            make_float2(fabsf(f0), fabsf(f1));
                    } else {
                        st.f2s[r] = make_float2(f0, f1);
                    }
                }
            }
            slot = (slot + 1 == 11) ? 0 : slot + 1;
        }
    }
    __syncthreads();
}

__global__ void __launch_bounds__(NTH, 2) fused_loss(
    const float* __restrict__ gen, const float* __restrict__ ir,
    const float* __restrict__ vi, float* __restrict__ out)
{
    extern __shared__ float smf[];
    const int t    = threadIdx.x;
    const int c0   = blockIdx.x * CT;
    const int y0   = blockIdx.y * BANDA;
    const int band = (blockIdx.y == 2) ? (HT - 2 * BANDA) : BANDA;
    const size_t pbase = (size_t)blockIdx.z * EPLANE;

    float4* hc4  = (float4*)(smf + OFF_HC);        // [p][slot11][ABP]
    float2* s2a  = (float2*)(smf + OFF_S2);        // [buf][p][r][ABP]
    float2* ppa  = (float2*)(smf + OFF_PP);        // [buf][p][r][ABP]
    float4* hac4 = (float4*)(smf + OFF_HAC);       // [p][slot11][CTP]
    float2* fb2  = (float2*)(smf + OFF_FB);        // [buf][p01][r][CTP]
    float*  red  = smf + OFF_RED;

    // roles: P2 = threads 0..206, P3a = threads 224..415
    const bool isA = t < 3 * ABP;                  // 207 threads
    const int  p2p = t / ABP;
    const int  p2j = t - p2p * ABP;
    const int  tb  = t - 224;
    const bool isB = (tb >= 0) && (tb < 3 * CTP);  // 192 threads
    const int  p3p = (tb >= 0) ? (tb >> 6) : 0;
    const int  p3i = (tb >= 0) ? (tb & (CTP - 1)) : 0;

    const float* xpA = (p2p == 0) ? (ir + pbase) : (p2p == 1) ? (vi + pbase) : (gen + pbase);
    const float* xpB = (p3p == 0) ? (ir + pbase) : (p3p == 1) ? (vi + pbase) : (gen + pbase);

    // thread-invariant column predicates
    const int cbase = c0 - 10 + 2 * p2j;
    const bool okc0 = (unsigned)(cbase)      < (unsigned)WD;
    const bool okc1 = (unsigned)(cbase + 2)  < (unsigned)WD;
    const bool okc2 = (unsigned)(cbase + 4)  < (unsigned)WD;
    const bool okc3 = (unsigned)(cbase + 6)  < (unsigned)WD;
    const bool okc4 = (unsigned)(cbase + 8)  < (unsigned)WD;
    const bool okc5 = (unsigned)(cbase + 10) < (unsigned)WD;
    const int  cab  = c0 - 5 + 2 * p2j;
    const bool okab0 = (unsigned)cab       < (unsigned)WD;
    const bool okab1 = (unsigned)(cab + 1) < (unsigned)WD;

    IterState st;
    st.SA = st.SB = st.TA = st.TB = make_float2(0.f, 0.f);
#pragma unroll
    for (int r = 0; r < RPB; ++r) st.f2s[r] = make_float2(0.f, 0.f);
    st.lacc = 0.f;

    const int iters = (band + 24) / RPB + 1;       // 50 or 49
    const int pmax  = (band + 20) / RPB;           // P2 active while i < pmax
    int iSteadyEnd  = (HT - y0 + 6) / 4 + 1;       // last-band row-bound
    if (iSteadyEnd > pmax) iSteadyEnd = pmax;
    if (iSteadyEnd < 7)    iSteadyEnd = 7;

    for (int i = 0; i < 7; ++i)
        iter_body<false>(i, y0, band, c0, pmax, isA, xpA, p2p, p2j, isB, xpB, p3p, p3i,
                         okc0, okc1, okc2, okc3, okc4, okc5, okab0, okab1,
                         hc4, s2a, ppa, hac4, fb2, st);
    for (int i = 7; i < iSteadyEnd; ++i)
        iter_body<true>(i, y0, band, c0, pmax, isA, xpA, p2p, p2j, isB, xpB, p3p, p3i,
                        okc0, okc1, okc2, okc3, okc4, okc5, okab0, okab1,
                        hc4, s2a, ppa, hac4, fb2, st);
    for (int i = iSteadyEnd; i < iters; ++i)
        iter_body<false>(i, y0, band, c0, pmax, isA, xpA, p2p, p2j, isB, xpB, p3p, p3i,
                         okc0, okc1, okc2, okc3, okc4, okc5, okab0, okab1,
                         hc4, s2a, ppa, hac4, fb2, st);

    // ---- block reduction + atomic ----------------------------------------
    float lacc = st.lacc;
#pragma unroll
    for (int o = 16; o; o >>= 1) lacc += __shfl_down_sync(0xffffffffu, lacc, o);
    if ((t & 31) == 0) red[t >> 5] = lacc;
    __syncthreads();
    if (t == 0) {
        float v = 0.f;
#pragma unroll
        for (int w = 0; w < NWARP; ++w) v += red[w];
        atomicAdd(out, v * SCALE);
    }
}

__global__ void zero_out(float* out) { out[0] = 0.f; }

// ---------------------------------------------------------------------------
extern "C" void kernel_launch(void* const* d_in, const int* in_sizes, int n_in,
                              void* d_out, int out_size) {
    const float* gen = (const float*)d_in[0];
    const float* ir  = (const float*)d_in[1];
    const float* vi  = (const float*)d_in[2];
    float* out = (float*)d_out;

    cudaFuncSetAttribute(fused_loss, cudaFuncAttributeMaxDynamicSharedMemorySize,
                         SMEM_BYTES);

    zero_out<<<1, 1>>>(out);
    dim3 grid(WD / CT, 3, NPL);   // (4, 3, 24) = 288 blocks
    fused_loss<<<grid, NTH, SMEM_BYTES>>>(gen, ir, vi, out);
}